// round 17
// baseline (speedup 1.0000x reference)
#include <cuda_runtime.h>
#include <cuda_fp16.h>
#include <math.h>
#include <stdint.h>

#define NPTS 8192
#define NSRC 4096
#define DIM  256
#define TILE 128
#define NT   (NPTS / TILE)          // 64
#define NBLK (NT * (NT + 1) / 2)    // 2080 upper-triangle tile pairs

// ---------------------------------------------------------------- scratch
// Device globals are zero-initialized at module load; writeout_kernel
// re-zeros the accumulators each run so graph replays start clean.
__device__ float  g_sq[NPTS];
__device__ double g_colsum[DIM];
__device__ double g_sumsq;
__device__ double g_acc;
__device__ __half g_h[NPTS * DIM];

// ---------------------------------------------------------------- helpers
__device__ __forceinline__ uint32_t smem_u32(const void* p) {
    uint32_t a;
    asm("{ .reg .u64 t; cvta.to.shared.u64 t, %1; cvt.u32.u64 %0, t; }" : "=r"(a) : "l"(p));
    return a;
}
#define CP_ASYNC16(dst, src) \
    asm volatile("cp.async.cg.shared.global [%0], [%1], 16;" :: "r"(dst), "l"(src))
#define CP_COMMIT() asm volatile("cp.async.commit_group;" ::: "memory")
#define CP_WAIT1()  asm volatile("cp.async.wait_group 1;" ::: "memory")

#define LDSM_X4(r0, r1, r2, r3, a) \
    asm volatile("ldmatrix.sync.aligned.m8n8.x4.shared.b16 {%0,%1,%2,%3}, [%4];" \
        : "=r"(r0), "=r"(r1), "=r"(r2), "=r"(r3) : "r"(a))

// fp16-accumulator MMA: D,C packed 2 halves/reg
#define MMA_F16A(d, a, b0, b1) \
    asm volatile("mma.sync.aligned.m16n8k16.row.col.f16.f16.f16.f16 " \
        "{%0,%1}, {%2,%3,%4,%5}, {%6,%7}, {%0,%1};" \
        : "+r"((d)[0]), "+r"((d)[1]) \
        : "r"((a)[0]), "r"((a)[1]), "r"((a)[2]), "r"((a)[3]), "r"(b0), "r"(b1))

#define EX2F(u, t) asm("ex2.approx.ftz.f32 %0, %1;" : "=f"(u) : "f"(t))

// packed f32x2 ops (sm_100+ base ISA)
#define PACK2(o, lo, hi) asm("mov.b64 %0, {%1, %2};" : "=l"(o) : "f"(lo), "f"(hi))
#define UNPACK2(lo, hi, v) asm("mov.b64 {%0, %1}, %2;" : "=f"(lo), "=f"(hi) : "l"(v))
#define MUL2(o, a, b) asm("mul.rn.f32x2 %0, %1, %2;" : "=l"(o) : "l"(a), "l"(b))
#define ADD2(o, a, b) asm("add.rn.f32x2 %0, %1, %2;" : "=l"(o) : "l"(a), "l"(b))
#define FMA2(o, a, b, c) asm("fma.rn.f32x2 %0, %1, %2, %3;" : "=l"(o) : "l"(a), "l"(b), "l"(c))

__device__ __forceinline__ const float* row_ptr(const float* src, const float* tgt, int i) {
    return (i < NSRC) ? (src + (size_t)i * DIM) : (tgt + (size_t)(i - NSRC) * DIM);
}

// ---------------------------------------------------------------- prep kernel
// 512 blocks x 256 threads; block handles 16 rows (warp -> 2 rows).
// Fused: fp16 convert + per-row ||x||^2 + column sums.
__global__ void prep_kernel(const float* __restrict__ src, const float* __restrict__ tgt) {
    __shared__ float cs[DIM];
    int tid  = threadIdx.x;
    int wid  = tid >> 5;
    int lane = tid & 31;
    cs[tid] = 0.f;
    __syncthreads();

    float col_acc[8] = {0, 0, 0, 0, 0, 0, 0, 0};
    float sq_acc = 0.f;

    int rbase = blockIdx.x * 16 + wid * 2;
#pragma unroll
    for (int rr = 0; rr < 2; rr++) {
        int row = rbase + rr;
        const float4* p4 = (const float4*)row_ptr(src, tgt, row);
        float s = 0.f;
#pragma unroll
        for (int t = 0; t < 2; t++) {
            float4 v = p4[lane + t * 32];
            float x[4] = {v.x, v.y, v.z, v.w};
            uint32_t hb[4];
#pragma unroll
            for (int k = 0; k < 4; k++) {
                s += x[k] * x[k];
                col_acc[t * 4 + k] += x[k];
                hb[k] = (uint32_t)__half_as_ushort(__float2half_rn(x[k]));
            }
            size_t q = (size_t)row * 64 + lane + t * 32;   // uint2 index (4 halves)
            ((uint2*)g_h)[q] = make_uint2(hb[0] | (hb[1] << 16), hb[2] | (hb[3] << 16));
        }
#pragma unroll
        for (int o = 16; o > 0; o >>= 1) s += __shfl_xor_sync(0xffffffffu, s, o);
        if (lane == 0) { g_sq[row] = s; sq_acc += s; }
    }
    if (lane == 0) atomicAdd(&g_sumsq, (double)sq_acc);

#pragma unroll
    for (int t = 0; t < 2; t++)
#pragma unroll
        for (int k = 0; k < 4; k++)
            atomicAdd(&cs[t * 128 + lane * 4 + k], col_acc[t * 4 + k]);
    __syncthreads();
    atomicAdd(&g_colsum[tid], (double)cs[tid]);
}

// ---------------------------------------------------------------- main tile kernel
// 256 threads, 8 warps (2x4), warp tile 64x32, CTA tile 128x128; 2 CTAs/SM.
// K chunk = 64: smem arrays per stage: A, B; each 128 rows x 144B (64 fp16 + 16 pad)
#define STRIDE_B    144
#define ARR_BYTES   (128 * STRIDE_B)        // 18432
#define STAGE_BYTES (2 * ARR_BYTES)         // 36864
#define NSTAGE      3
#define NCHUNK      4
#define DYN_SMEM    (NSTAGE * STAGE_BYTES)  // 110592

__global__ void __launch_bounds__(256, 2)
mmd_mma_kernel() {
    extern __shared__ char dsmem[];
    __shared__ float  red[8];
    __shared__ float  s_cexp;
    __shared__ float  sqa_s[TILE];
    __shared__ float  sqb_s[TILE];

    uint32_t dyn_u = smem_u32(dsmem);
    int tid  = threadIdx.x;
    int wid  = tid >> 5;
    int lane = tid & 31;
    int wm   = wid & 1;       // 2 warp-rows of 64
    int wn   = wid >> 1;      // 4 warp-cols of 32

    // decode linear block id -> (bi, bj), bi <= bj
    int b = blockIdx.x;
    float fb = (float)b;
    int bi = (int)((2.0f * NT + 1.0f - sqrtf((2.0f * NT + 1.0f) * (2.0f * NT + 1.0f) - 8.0f * fb)) * 0.5f);
    if (bi < 0) bi = 0;
    if (bi >= NT) bi = NT - 1;
#define TRI_START(i) ((i) * NT - (i) * ((i) - 1) / 2)
    while (bi + 1 < NT && TRI_START(bi + 1) <= b) bi++;
    while (bi > 0 && TRI_START(bi) > b) bi--;
    int bj = bi + (b - TRI_START(bi));
#undef TRI_START
    int row0 = bi * TILE;
    int col0 = bj * TILE;

    const char* gbase[2];
    gbase[0] = (const char*)(g_h + (size_t)row0 * DIM);   // A
    gbase[1] = (const char*)(g_h + (size_t)col0 * DIM);   // B

    // loader: chunk c = k bytes [c*128, c*128+128); 2048 x 16B; 256 threads -> 8 each
#define ISSUE_LOADS(c, s) do { \
    _Pragma("unroll") \
    for (int i = 0; i < 8; i++) { \
        int arr = i >> 2; \
        int rem = tid + (i & 3) * 256;      /* 0..1023 */ \
        int row = rem >> 3; \
        int q   = rem & 7; \
        const char* srcp = gbase[arr] + (size_t)row * 512 + (c) * 128 + q * 16; \
        uint32_t dst = dyn_u + (s) * STAGE_BYTES + arr * ARR_BYTES + row * STRIDE_B + q * 16; \
        CP_ASYNC16(dst, srcp); \
    } \
    CP_COMMIT(); \
} while (0)

    ISSUE_LOADS(0, 0);
    ISSUE_LOADS(1, 1);

    if (tid < TILE) {
        sqa_s[tid] = g_sq[row0 + tid];
        sqb_s[tid] = g_sq[col0 + tid];
    }

    // Prefetch bandwidth-reduction inputs now; the loads complete under the
    // mainloop and the actual reduction happens after it (no pre-loop stall).
    double my_cs, my_ssq;
    asm volatile("ld.global.nc.f64 %0, [%1];" : "=d"(my_cs)  : "l"(g_colsum + tid));
    asm volatile("ld.global.nc.f64 %0, [%1];" : "=d"(my_ssq) : "l"(&g_sumsq));

    uint32_t acc[4][4][2];    // fp16x2 accumulators
#pragma unroll
    for (int mi = 0; mi < 4; mi++)
#pragma unroll
        for (int ni = 0; ni < 4; ni++) {
            acc[mi][ni][0] = 0u;
            acc[mi][ni][1] = 0u;
        }

    // ldmatrix lane-address components
    int a_m    = lane >> 3;
    int a_rofs = ((a_m & 1) << 3) + (lane & 7);
    int a_koff = (a_m >> 1) << 4;
    int b_nofs = ((a_m >> 1) << 3) + (lane & 7);
    int b_koff = (a_m & 1) << 4;

    // fragment loader (double-buffered)
#define LOAD_FRAGS(buf, stage_u, ks) do { \
    _Pragma("unroll") \
    for (int mi = 0; mi < 4; mi++) { \
        int r = wm * 64 + mi * 16 + a_rofs; \
        uint32_t ad = (stage_u) + r * STRIDE_B + (ks) * 32 + a_koff; \
        LDSM_X4(Af[buf][mi][0], Af[buf][mi][1], Af[buf][mi][2], Af[buf][mi][3], ad); \
    } \
    _Pragma("unroll") \
    for (int pi = 0; pi < 2; pi++) { \
        int nl = wn * 32 + pi * 16 + b_nofs; \
        uint32_t bd = (stage_u) + ARR_BYTES + nl * STRIDE_B + (ks) * 32 + b_koff; \
        LDSM_X4(Bf[buf][pi][0], Bf[buf][pi][1], Bf[buf][pi][2], Bf[buf][pi][3], bd); \
    } \
} while (0)

#define DO_MMAS(buf) do { \
    _Pragma("unroll") \
    for (int mi = 0; mi < 4; mi++) { \
        _Pragma("unroll") \
        for (int ni = 0; ni < 4; ni++) { \
            int pi = ni >> 1, h = (ni & 1) * 2; \
            MMA_F16A(acc[mi][ni], Af[buf][mi], Bf[buf][pi][h], Bf[buf][pi][h + 1]); \
        } \
    } \
} while (0)

    uint32_t Af[2][4][4], Bf[2][2][4];

    for (int c = 0; c < NCHUNK; c++) {
        CP_WAIT1();           // chunk c resident
        __syncthreads();      // all warps past chunk c-1 compute; stage (c+2)%3 free
        if (c + 2 < NCHUNK) ISSUE_LOADS(c + 2, (c + 2) % NSTAGE);
        else CP_COMMIT();     // empty group keeps wait_group accounting exact

        uint32_t stage_u = dyn_u + (c % NSTAGE) * STAGE_BYTES;
        LOAD_FRAGS(0, stage_u, 0);
#pragma unroll
        for (int ks = 0; ks < 4; ks++) {
            int cur = ks & 1;
            if (ks < 3) LOAD_FRAGS(cur ^ 1, stage_u, ks + 1);
            DO_MMAS(cur);
        }
        // no trailing sync: next chunk's top barrier orders reads before refill
    }

    // ---- bandwidth constant (lazy; prefetched loads have long completed) ----
    {
        float cv = (float)my_cs;
        cv *= cv;
#pragma unroll
        for (int o = 16; o > 0; o >>= 1) cv += __shfl_xor_sync(0xffffffffu, cv, o);
        if (lane == 0) red[wid] = cv;
        __syncthreads();
        if (tid == 0) {
            float sc = 0.f;
#pragma unroll
            for (int i = 0; i < 8; i++) sc += red[i];
            double n = (double)NPTS;
            double sumL2 = 2.0 * n * my_ssq - 2.0 * (double)sc;
            double bw = sumL2 / (n * n - n) / 4.0;   // / KERNEL_MUL^(KERNEL_NUM//2)
            s_cexp = (float)(-1.0 / (16.0 * bw * 0.6931471805599453));
        }
        __syncthreads();
    }

    // ---------------- epilogue: packed f32x2, full fp32 precision ----------------
    // element map: row = wm*64+mi*16 + lane/4 + (p)*8 ; col = wn*32+ni*8 + (lane%4)*2 + {0,1}
    float cexp = s_cexp;
    float m2c  = -2.f * cexp;
    int rlo = lane >> 2;
    int cl0 = (lane & 3) * 2;

    uint64_t M2C, tB2[4];
    PACK2(M2C, m2c, m2c);
#pragma unroll
    for (int ni = 0; ni < 4; ni++) {
        float b0 = cexp * sqb_s[wn * 32 + ni * 8 + cl0];
        float b1 = cexp * sqb_s[wn * 32 + ni * 8 + cl0 + 1];
        PACK2(tB2[ni], b0, b1);
    }

    uint64_t S2;
    PACK2(S2, 0.f, 0.f);
#pragma unroll
    for (int mi = 0; mi < 4; mi++) {
        uint64_t tA2[2];
        {
            float a0 = cexp * sqa_s[wm * 64 + mi * 16 + rlo];
            float a1 = cexp * sqa_s[wm * 64 + mi * 16 + rlo + 8];
            PACK2(tA2[0], a0, a0);
            PACK2(tA2[1], a1, a1);
        }
#pragma unroll
        for (int ni = 0; ni < 4; ni++) {
#pragma unroll
            for (int p = 0; p < 2; p++) {
                float2 d = __half22float2(*(__half2*)&acc[mi][ni][p]);
                uint64_t D, TAB, T;
                PACK2(D, d.x, d.y);
                ADD2(TAB, tA2[p], tB2[ni]);
                FMA2(T, D, M2C, TAB);          // t = cexp*(sqa + sqb - 2*dot)
                float t0, t1, u0, u1;
                UNPACK2(t0, t1, T);
                EX2F(u0, t0);
                EX2F(u1, t1);
                uint64_t U, U2, U4, U8, A, B, C, Dp;
                PACK2(U, u0, u1);
                MUL2(U2, U, U);
                MUL2(U4, U2, U2);
                MUL2(U8, U4, U4);
                FMA2(A, U, U, U);              // u^2 + u
                FMA2(B, U4, U4, U4);           // u^8 + u^4
                FMA2(C, U8, U8, B);            // u^16 + u^8 + u^4
                ADD2(Dp, A, C);                // full 5-term kernel sum
                ADD2(S2, S2, Dp);
            }
        }
    }
    float s, shi;
    UNPACK2(s, shi, S2);
    s += shi;

    // warp-shuffle reduce, then tiny cross-warp fold
#pragma unroll
    for (int o = 16; o > 0; o >>= 1) s += __shfl_xor_sync(0xffffffffu, s, o);
    __syncthreads();          // red[] reuse after cexp reduction
    if (lane == 0) red[wid] = s;
    __syncthreads();
    if (tid == 0) {
        float t = 0.f;
#pragma unroll
        for (int i = 0; i < 8; i++) t += red[i];
        float w  = (bi == bj) ? 1.f : 2.f;
        float sr = (row0 < NSRC) ? 1.f : -1.f;
        float sc = (col0 < NSRC) ? 1.f : -1.f;
        atomicAdd(&g_acc, (double)(t * w * sr * sc));
    }
}

// Writes result and re-zeros accumulators so the next graph replay starts clean.
__global__ void writeout_kernel(float* out) {
    int t = threadIdx.x;
    if (t == 0) out[0] = (float)(g_acc / ((double)NSRC * (double)NSRC));
    if (t < DIM) g_colsum[t] = 0.0;
    if (t == 0) { g_sumsq = 0.0; g_acc = 0.0; }
}

// ---------------------------------------------------------------- launch
extern "C" void kernel_launch(void* const* d_in, const int* in_sizes, int n_in,
                              void* d_out, int out_size) {
    const float* src = (const float*)d_in[0];
    const float* tgt = (const float*)d_in[1];
    float* out = (float*)d_out;

    cudaFuncSetAttribute(mmd_mma_kernel, cudaFuncAttributeMaxDynamicSharedMemorySize, DYN_SMEM);

    prep_kernel<<<NPTS / 16, 256>>>(src, tgt);     // fp16 convert + norms + colsums fused
    mmd_mma_kernel<<<NBLK, 256, DYN_SMEM>>>();
    writeout_kernel<<<1, 256>>>(out);
}